// round 11
// baseline (speedup 1.0000x reference)
// R11: packed fma.rn.f32x2 GEMMs (duplicated-activation smem layout, dynamic smem);
//      gather/CSR/pool unchanged from R10.
#include <cuda_runtime.h>
#include <cuda_fp16.h>
#include <math.h>
#include <float.h>

#define NN 100000
#define EE 1200000
#define FD 64
#define NG 1024
#define NT 12
#define CHID 128
#define EPS 1e-5f
#define NB1 98   // (NN+1023)/1024

#define XS2_STRIDE 132                       // floats per duplicated row
#define DYN_BYTES ((64 * XS2_STRIDE + 64 * 64) * 4)   // xs2 + Ws/aggs

typedef unsigned long long u64;

__device__ __forceinline__ void ffma2(u64 &d, u64 a, u64 b) {
    asm("fma.rn.f32x2 %0, %1, %2, %0;" : "+l"(d) : "l"(a), "l"(b));
}

// ---------------- scratch ----------------
__device__ __half g_mh[(size_t)NN * FD];  // projected messages (fp16)
__device__ float g_h1[(size_t)NN * FD];
__device__ float g_h2[(size_t)NN * FD];
__device__ float g_w[NN];
__device__ int   g_deg[NN + 1];
__device__ int   g_off[NN + 1];
__device__ int   g_cur[NN];
__device__ int   g_esrc[EE];
__device__ int   g_bsum[128];
__device__ int   g_bpre[128];
__device__ float g_stats1[2 * FD];
__device__ float g_stats2[2 * FD];
__device__ float g_statsC[2 * CHID];
__device__ float g_hg[(size_t)NG * 2 * FD];
__device__ float g_z[(size_t)NG * CHID];

// ---------------- zero ----------------
__global__ void k_zero() {
    int i = blockIdx.x * blockDim.x + threadIdx.x;
    if (i < NN + 1) g_deg[i] = 0;
    if (i < NN) g_cur[i] = 0;
    if (i < 2 * FD) { g_stats1[i] = 0.f; g_stats2[i] = 0.f; }
    if (i < 2 * CHID) g_statsC[i] = 0.f;
}

// ---------------- CSR build ----------------
__global__ void k_deg(const int* __restrict__ dst) {
    int i = blockIdx.x * blockDim.x + threadIdx.x;
    if (i < EE / 4) {
        int4 d = ((const int4*)dst)[i];
        atomicAdd(&g_deg[d.x], 1);
        atomicAdd(&g_deg[d.y], 1);
        atomicAdd(&g_deg[d.z], 1);
        atomicAdd(&g_deg[d.w], 1);
    }
}

__global__ __launch_bounds__(1024) void k_scan1() {
    int tid = threadIdx.x;
    int i = blockIdx.x * 1024 + tid;
    int d = (i < NN) ? g_deg[i] : 0;
    int lane = tid & 31, wid = tid >> 5;
    int v = d;
    #pragma unroll
    for (int o = 1; o < 32; o <<= 1) {
        int t = __shfl_up_sync(0xffffffffu, v, o);
        if (lane >= o) v += t;
    }
    __shared__ int ws[32];
    if (lane == 31) ws[wid] = v;
    __syncthreads();
    if (wid == 0) {
        int u = ws[lane];
        #pragma unroll
        for (int o = 1; o < 32; o <<= 1) {
            int t = __shfl_up_sync(0xffffffffu, u, o);
            if (lane >= o) u += t;
        }
        ws[lane] = u;
    }
    __syncthreads();
    int base = wid ? ws[wid - 1] : 0;
    if (i < NN) g_off[i] = base + v - d;
    if (tid == 0) g_bsum[blockIdx.x] = ws[31];
}

__global__ void k_scan2() {
    __shared__ int sh[128];
    int tid = threadIdx.x;
    int v = (tid < NB1) ? g_bsum[tid] : 0;
    sh[tid] = v;
    __syncthreads();
    for (int o = 1; o < 128; o <<= 1) {
        int t = (tid >= o) ? sh[tid - o] : 0;
        __syncthreads();
        sh[tid] += t;
        __syncthreads();
    }
    if (tid < NB1) g_bpre[tid] = sh[tid] - v;
}

__global__ void k_scatter(const int* __restrict__ src, const int* __restrict__ dst) {
    int i = blockIdx.x * blockDim.x + threadIdx.x;
    if (i < EE / 4) {
        int4 s = ((const int4*)src)[i];
        int4 d = ((const int4*)dst)[i];
        int o0 = __ldg(&g_off[d.x]) + __ldg(&g_bpre[d.x >> 10]);
        int o1 = __ldg(&g_off[d.y]) + __ldg(&g_bpre[d.y >> 10]);
        int o2 = __ldg(&g_off[d.z]) + __ldg(&g_bpre[d.z >> 10]);
        int o3 = __ldg(&g_off[d.w]) + __ldg(&g_bpre[d.w >> 10]);
        g_esrc[o0 + atomicAdd(&g_cur[d.x], 1)] = s.x;
        g_esrc[o1 + atomicAdd(&g_cur[d.y], 1)] = s.y;
        g_esrc[o2 + atomicAdd(&g_cur[d.z], 1)] = s.z;
        g_esrc[o3 + atomicAdd(&g_cur[d.w], 1)] = s.w;
    }
}

__device__ __forceinline__ int node_off(int v) {
    return g_off[v] + g_bpre[v >> 10];
}

// ---- shared helper: fill duplicated BN(x) tile + weight tile, run f32x2 GEMM ----
// xs2: [64][XS2_STRIDE] duplicated; Ws: [64*64]; accp: 4 rows x 2 col-pairs.
__device__ __forceinline__ void gemm_f32x2(
    const float* xs2, const float* Ws, int r0, int c0, u64 accp[4][2])
{
    const ulonglong2* xr0 = (const ulonglong2*)(xs2 + (size_t)(r0 + 0) * XS2_STRIDE);
    const ulonglong2* xr1 = (const ulonglong2*)(xs2 + (size_t)(r0 + 1) * XS2_STRIDE);
    const ulonglong2* xr2 = (const ulonglong2*)(xs2 + (size_t)(r0 + 2) * XS2_STRIDE);
    const ulonglong2* xr3 = (const ulonglong2*)(xs2 + (size_t)(r0 + 3) * XS2_STRIDE);
    #pragma unroll 4
    for (int k2 = 0; k2 < 32; k2++) {      // two k-steps per iter
        ulonglong2 A0 = xr0[k2];
        ulonglong2 A1 = xr1[k2];
        ulonglong2 A2 = xr2[k2];
        ulonglong2 A3 = xr3[k2];
        ulonglong2 B0 = *(const ulonglong2*)(Ws + (2 * k2 + 0) * 64 + c0);
        ulonglong2 B1 = *(const ulonglong2*)(Ws + (2 * k2 + 1) * 64 + c0);
        ffma2(accp[0][0], A0.x, B0.x); ffma2(accp[0][1], A0.x, B0.y);
        ffma2(accp[1][0], A1.x, B0.x); ffma2(accp[1][1], A1.x, B0.y);
        ffma2(accp[2][0], A2.x, B0.x); ffma2(accp[2][1], A2.x, B0.y);
        ffma2(accp[3][0], A3.x, B0.x); ffma2(accp[3][1], A3.x, B0.y);
        ffma2(accp[0][0], A0.y, B1.x); ffma2(accp[0][1], A0.y, B1.y);
        ffma2(accp[1][0], A1.y, B1.x); ffma2(accp[1][1], A1.y, B1.y);
        ffma2(accp[2][0], A2.y, B1.x); ffma2(accp[2][1], A2.y, B1.y);
        ffma2(accp[3][0], A3.y, B1.x); ffma2(accp[3][1], A3.y, B1.y);
    }
}

__device__ __forceinline__ void fill_xs2_dup(
    float* xs2, const float* __restrict__ x, int row0, int tid,
    const float* scb, const float* shb)
{
    #pragma unroll
    for (int q = 0; q < 4; q++) {
        int lin = tid + q * 256;
        int r = lin >> 4;
        int c4 = (lin & 15) * 4;
        float4 v = make_float4(0.f, 0.f, 0.f, 0.f);
        if (row0 + r < NN) v = *(const float4*)(x + (size_t)(row0 + r) * 64 + c4);
        float o0 = v.x * scb[c4 + 0] + shb[c4 + 0];
        float o1 = v.y * scb[c4 + 1] + shb[c4 + 1];
        float o2 = v.z * scb[c4 + 2] + shb[c4 + 2];
        float o3 = v.w * scb[c4 + 3] + shb[c4 + 3];
        float2* row = (float2*)(xs2 + (size_t)r * XS2_STRIDE);
        row[c4 + 0] = make_float2(o0, o0);
        row[c4 + 1] = make_float2(o1, o1);
        row[c4 + 2] = make_float2(o2, o2);
        row[c4 + 3] = make_float2(o3, o3);
    }
}

// ---------------- GEMM: m = BN(x) @ W  -> fp16 ----------------
__global__ __launch_bounds__(256) void k_gemm(
    const float* __restrict__ x,
    const float* __restrict__ stats, const float* __restrict__ gamma, const float* __restrict__ beta,
    const float* __restrict__ W, __half* __restrict__ out)
{
    extern __shared__ float dyn[];
    float* xs2 = dyn;                       // 64 * XS2_STRIDE
    float* Ws  = dyn + 64 * XS2_STRIDE;     // 64 * 64
    __shared__ float scb[64], shb[64];
    int tid = threadIdx.x;

    if (tid < 64) {
        float sc = 1.f, sh = 0.f;
        if (stats) {
            float mu  = stats[tid] * (1.f / NN);
            float var = stats[64 + tid] * (1.f / NN) - mu * mu;
            float rs  = rsqrtf(var + EPS);
            sc = gamma[tid] * rs;
            sh = beta[tid] - mu * sc;
        }
        scb[tid] = sc; shb[tid] = sh;
    }
    #pragma unroll
    for (int q = 0; q < 16; q++) {
        int lin = tid + q * 256;
        Ws[lin] = W[lin];
    }
    __syncthreads();

    int row0 = blockIdx.x * 64;
    fill_xs2_dup(xs2, x, row0, tid, scb, shb);
    __syncthreads();

    int tx = tid & 15, ty = tid >> 4;
    int r0 = ty * 4, c0 = tx * 4;
    u64 accp[4][2] = {};
    gemm_f32x2(xs2, Ws, r0, c0, accp);

    #pragma unroll
    for (int i = 0; i < 4; i++) {
        int r = row0 + r0 + i;
        if (r < NN) {
            float2 p01 = *(float2*)&accp[i][0];
            float2 p23 = *(float2*)&accp[i][1];
            __half2 h0 = __floats2half2_rn(p01.x, p01.y);
            __half2 h1 = __floats2half2_rn(p23.x, p23.y);
            *(uint2*)(out + (size_t)r * 64 + c0) = make_uint2(*(unsigned*)&h0, *(unsigned*)&h1);
        }
    }
}

// ---- post (fused): residual f32x2 GEMM + quarter-warp fp16 gather + bias/relu + BN stats ----
__global__ __launch_bounds__(256) void k_post(
    const float* __restrict__ x,
    const float* __restrict__ stats, const float* __restrict__ gamma, const float* __restrict__ beta,
    const float* __restrict__ rW, const float* __restrict__ rb, const float* __restrict__ bias,
    float* __restrict__ outh, float* __restrict__ stats_out)
{
    extern __shared__ float dyn[];
    float* xs2 = dyn;                       // 64 * XS2_STRIDE (duplicated BN(x))
    float* Ws  = dyn + 64 * XS2_STRIDE;     // rW during GEMM, then agg tile (64*64)
    __shared__ float scb[64], shb[64];
    __shared__ float s_sum[64], s_sq[64];
    int tid = threadIdx.x;
    int lane = tid & 31, wi = tid >> 5;

    if (tid < 64) {
        float sc = 1.f, sh = 0.f;
        if (stats) {
            float mu  = stats[tid] * (1.f / NN);
            float var = stats[64 + tid] * (1.f / NN) - mu * mu;
            float rs  = rsqrtf(var + EPS);
            sc = gamma[tid] * rs;
            sh = beta[tid] - mu * sc;
        }
        scb[tid] = sc; shb[tid] = sh;
        s_sum[tid] = 0.f; s_sq[tid] = 0.f;
    }
    #pragma unroll
    for (int q = 0; q < 16; q++) {
        int lin = tid + q * 256;
        Ws[lin] = rW[lin];
    }
    __syncthreads();

    int row0 = blockIdx.x * 64;
    fill_xs2_dup(xs2, x, row0, tid, scb, shb);
    __syncthreads();

    int tx = tid & 15, ty = tid >> 4;
    int r0 = ty * 4, c0 = tx * 4;
    u64 accp[4][2] = {};
    gemm_f32x2(xs2, Ws, r0, c0, accp);
    __syncthreads();   // done with rW in Ws

    // ---- gather: warp split into four 8-lane quarters, one node each; uint4/lane = full row ----
    float* aggs = Ws;
    const uint4* m8 = (const uint4*)g_mh;           // 8 uint4 per node row (128 B)
    int lane8 = lane & 7;
    int qb    = lane & 24;                           // quarter base lane: 0,8,16,24
    for (int t = 0; t < 2; t++) {
        int r = wi * 8 + t * 4 + (qb >> 3);
        int v = row0 + r;
        float a0 = 0.f, a1 = 0.f, a2 = 0.f, a3 = 0.f;
        float a4 = 0.f, a5 = 0.f, a6 = 0.f, a7 = 0.f;
        int s = 0, cnt = 0;
        if (v < NN) {
            s = node_off(v);
            int e = (v + 1 < NN) ? node_off(v + 1) : EE;
            cnt = e - s;
        }
        int m = max(cnt, __shfl_xor_sync(0xffffffffu, cnt, 8));
        int iters = max(m, __shfl_xor_sync(0xffffffffu, m, 16));
        for (int base = 0; base < iters; base += 8) {
            int my = base + lane8;
            int idx = (my < cnt) ? __ldg(&g_esrc[s + my]) : -1;
            #pragma unroll
            for (int g = 0; g < 8; g += 4) {
                int s0 = __shfl_sync(0xffffffffu, idx, qb + g + 0);
                int s1 = __shfl_sync(0xffffffffu, idx, qb + g + 1);
                int s2 = __shfl_sync(0xffffffffu, idx, qb + g + 2);
                int s3 = __shfl_sync(0xffffffffu, idx, qb + g + 3);
                uint4 z = make_uint4(0u, 0u, 0u, 0u);
                uint4 q0 = (s0 >= 0) ? __ldg(&m8[(size_t)s0 * 8 + lane8]) : z;
                uint4 q1 = (s1 >= 0) ? __ldg(&m8[(size_t)s1 * 8 + lane8]) : z;
                uint4 q2 = (s2 >= 0) ? __ldg(&m8[(size_t)s2 * 8 + lane8]) : z;
                uint4 q3 = (s3 >= 0) ? __ldg(&m8[(size_t)s3 * 8 + lane8]) : z;
                float2 f0, f1, f2, f3;
                f0 = __half22float2(*(__half2*)&q0.x); f1 = __half22float2(*(__half2*)&q1.x);
                f2 = __half22float2(*(__half2*)&q2.x); f3 = __half22float2(*(__half2*)&q3.x);
                a0 += (f0.x + f1.x) + (f2.x + f3.x);
                a1 += (f0.y + f1.y) + (f2.y + f3.y);
                f0 = __half22float2(*(__half2*)&q0.y); f1 = __half22float2(*(__half2*)&q1.y);
                f2 = __half22float2(*(__half2*)&q2.y); f3 = __half22float2(*(__half2*)&q3.y);
                a2 += (f0.x + f1.x) + (f2.x + f3.x);
                a3 += (f0.y + f1.y) + (f2.y + f3.y);
                f0 = __half22float2(*(__half2*)&q0.z); f1 = __half22float2(*(__half2*)&q1.z);
                f2 = __half22float2(*(__half2*)&q2.z); f3 = __half22float2(*(__half2*)&q3.z);
                a4 += (f0.x + f1.x) + (f2.x + f3.x);
                a5 += (f0.y + f1.y) + (f2.y + f3.y);
                f0 = __half22float2(*(__half2*)&q0.w); f1 = __half22float2(*(__half2*)&q1.w);
                f2 = __half22float2(*(__half2*)&q2.w); f3 = __half22float2(*(__half2*)&q3.w);
                a6 += (f0.x + f1.x) + (f2.x + f3.x);
                a7 += (f0.y + f1.y) + (f2.y + f3.y);
            }
        }
        if (v < NN) {
            float* dst = aggs + r * 64 + lane8 * 8;
            *(float4*)(dst + 0) = make_float4(a0, a1, a2, a3);
            *(float4*)(dst + 4) = make_float4(a4, a5, a6, a7);
        }
    }
    __syncthreads();

    // ---- epilogue ----
    float4 b4  = *(const float4*)(bias + c0);
    float4 rb4 = *(const float4*)(rb + c0);
    float lsum[4] = {0.f, 0.f, 0.f, 0.f};
    float lsq[4]  = {0.f, 0.f, 0.f, 0.f};
    #pragma unroll
    for (int i = 0; i < 4; i++) {
        int r = row0 + r0 + i;
        if (r < NN) {
            float2 p01 = *(float2*)&accp[i][0];
            float2 p23 = *(float2*)&accp[i][1];
            float4 av = *(const float4*)(aggs + (r0 + i) * 64 + c0);
            float h0 = fmaxf(av.x + b4.x, 0.f) + fmaxf(p01.x + rb4.x, 0.f);
            float h1 = fmaxf(av.y + b4.y, 0.f) + fmaxf(p01.y + rb4.y, 0.f);
            float h2 = fmaxf(av.z + b4.z, 0.f) + fmaxf(p23.x + rb4.z, 0.f);
            float h3 = fmaxf(av.w + b4.w, 0.f) + fmaxf(p23.y + rb4.w, 0.f);
            *(float4*)(outh + (size_t)r * 64 + c0) = make_float4(h0, h1, h2, h3);
            lsum[0] += h0; lsq[0] += h0 * h0;
            lsum[1] += h1; lsq[1] += h1 * h1;
            lsum[2] += h2; lsq[2] += h2 * h2;
            lsum[3] += h3; lsq[3] += h3 * h3;
        }
    }
    #pragma unroll
    for (int j = 0; j < 4; j++) {
        atomicAdd(&s_sum[c0 + j], lsum[j]);
        atomicAdd(&s_sq[c0 + j], lsq[j]);
    }
    __syncthreads();
    if (tid < 64) {
        atomicAdd(&stats_out[tid], s_sum[tid]);
        atomicAdd(&stats_out[64 + tid], s_sq[tid]);
    }
}

// ---------------- atom weights ----------------
__global__ __launch_bounds__(256) void k_wts(
    const float* __restrict__ gamma, const float* __restrict__ beta,
    const float* __restrict__ awW, const float* __restrict__ awb)
{
    int gt = blockIdx.x * blockDim.x + threadIdx.x;
    int v = gt >> 5;
    int lane = gt & 31;
    if (v >= NN) return;
    int f0 = 2 * lane, f1 = f0 + 1;
    float mu0  = g_stats2[f0] * (1.f / NN);
    float var0 = g_stats2[64 + f0] * (1.f / NN) - mu0 * mu0;
    float sc0  = gamma[f0] * rsqrtf(var0 + EPS);
    float sh0  = beta[f0] - mu0 * sc0;
    float mu1  = g_stats2[f1] * (1.f / NN);
    float var1 = g_stats2[64 + f1] * (1.f / NN) - mu1 * mu1;
    float sc1  = gamma[f1] * rsqrtf(var1 + EPS);
    float sh1  = beta[f1] - mu1 * sc1;
    float2 h = ((const float2*)g_h2)[(size_t)v * 32 + lane];
    float p = (h.x * sc0 + sh0) * awW[f0] + (h.y * sc1 + sh1) * awW[f1];
    #pragma unroll
    for (int o = 16; o; o >>= 1) p += __shfl_down_sync(0xffffffffu, p, o);
    if (lane == 0) g_w[v] = 1.f / (1.f + __expf(-(p + awb[0])));
}

// ---------------- pooling ----------------
__global__ __launch_bounds__(64) void k_pool(
    const int* __restrict__ ngr,
    const float* __restrict__ gamma, const float* __restrict__ beta)
{
    int g = blockIdx.x;
    int j = threadIdx.x;
    __shared__ int bnd[2];
    if (j < 2) {
        int key = g + j;
        int lo = 0, hi = NN;
        while (lo < hi) {
            int mid = (lo + hi) >> 1;
            if (ngr[mid] < key) lo = mid + 1; else hi = mid;
        }
        bnd[j] = lo;
    }
    float mu  = g_stats2[j] * (1.f / NN);
    float var = g_stats2[64 + j] * (1.f / NN) - mu * mu;
    float rs  = rsqrtf(var + EPS);
    float sc  = gamma[j] * rs;
    float sh  = beta[j] - mu * sc;
    __syncthreads();

    int s = bnd[0], e = bnd[1];
    float sum = 0.f, mx = -FLT_MAX;
    int n = s;
    for (; n + 4 <= e; n += 4) {
        float h0 = g_h2[(size_t)(n + 0) * 64 + j];
        float h1 = g_h2[(size_t)(n + 1) * 64 + j];
        float h2 = g_h2[(size_t)(n + 2) * 64 + j];
        float h3 = g_h2[(size_t)(n + 3) * 64 + j];
        float w0 = __ldg(&g_w[n + 0]);
        float w1 = __ldg(&g_w[n + 1]);
        float w2 = __ldg(&g_w[n + 2]);
        float w3 = __ldg(&g_w[n + 3]);
        h0 = h0 * sc + sh; h1 = h1 * sc + sh; h2 = h2 * sc + sh; h3 = h3 * sc + sh;
        sum += h0 * w0 + h1 * w1 + h2 * w2 + h3 * w3;
        mx = fmaxf(fmaxf(fmaxf(mx, h0), fmaxf(h1, h2)), h3);
    }
    for (; n < e; n++) {
        float h = g_h2[(size_t)n * 64 + j] * sc + sh;
        sum += h * __ldg(&g_w[n]);
        mx = fmaxf(mx, h);
    }
    g_hg[(size_t)g * 128 + j]      = sum;
    g_hg[(size_t)g * 128 + 64 + j] = mx;
}

// ---------------- classifier layer 1 ----------------
__global__ __launch_bounds__(128) void k_cls1(const float* __restrict__ W, const float* __restrict__ b) {
    __shared__ float xs[8][128];
    int tid = threadIdx.x;
    int row0 = blockIdx.x * 8;
    #pragma unroll
    for (int q = 0; q < 8; q++) {
        int lin = tid + q * 128;
        xs[lin >> 7][lin & 127] = g_hg[(size_t)row0 * 128 + lin];
    }
    __syncthreads();
    int j = tid;
    float acc[8] = {};
    for (int k = 0; k < 128; k++) {
        float w = __ldg(&W[k * 128 + j]);
        #pragma unroll
        for (int r = 0; r < 8; r++) acc[r] += xs[r][k] * w;
    }
    float bj = b[j];
    float lsum = 0.f, lsq = 0.f;
    #pragma unroll
    for (int r = 0; r < 8; r++) {
        float z = fmaxf(acc[r] + bj, 0.f);
        g_z[(size_t)(row0 + r) * 128 + j] = z;
        lsum += z; lsq += z * z;
    }
    atomicAdd(&g_statsC[j], lsum);
    atomicAdd(&g_statsC[128 + j], lsq);
}

// ---------------- classifier layer 2 ----------------
__global__ __launch_bounds__(256) void k_cls2(
    const float* __restrict__ cg, const float* __restrict__ cb,
    const float* __restrict__ W2, const float* __restrict__ b2, float* __restrict__ out)
{
    __shared__ float sc[128], sh[128];
    int tid = threadIdx.x;
    if (tid < 128) {
        float mu  = g_statsC[tid] * (1.f / NG);
        float var = g_statsC[128 + tid] * (1.f / NG) - mu * mu;
        float rs  = rsqrtf(var + EPS);
        float s = cg[tid] * rs;
        sc[tid] = s;
        sh[tid] = cb[tid] - mu * s;
    }
    __syncthreads();
    int idx = blockIdx.x * 256 + tid;
    if (idx >= NG * NT) return;
    int r = idx / NT, t = idx - r * NT;
    float acc = b2[t];
    for (int k = 0; k < 128; k++)
        acc += (g_z[(size_t)r * 128 + k] * sc[k] + sh[k]) * __ldg(&W2[k * NT + t]);
    out[idx] = acc;
}

// ---------------- launch (single stream, graph-capture safe) ----------------
extern "C" void kernel_launch(void* const* d_in, const int* in_sizes, int n_in,
                              void* d_out, int out_size) {
    const float* feats = (const float*)d_in[0];
    const int*   src   = (const int*)d_in[1];
    const int*   dst   = (const int*)d_in[2];
    const int*   ngr   = (const int*)d_in[3];
    const float* W0  = (const float*)d_in[4];
    const float* b0  = (const float*)d_in[5];
    const float* rW0 = (const float*)d_in[6];
    const float* rb0 = (const float*)d_in[7];
    const float* g0  = (const float*)d_in[8];
    const float* be0 = (const float*)d_in[9];
    const float* W1  = (const float*)d_in[10];
    const float* b1  = (const float*)d_in[11];
    const float* rW1 = (const float*)d_in[12];
    const float* rb1 = (const float*)d_in[13];
    const float* g1  = (const float*)d_in[14];
    const float* be1 = (const float*)d_in[15];
    const float* awW = (const float*)d_in[16];
    const float* awb = (const float*)d_in[17];
    const float* c1W = (const float*)d_in[18];
    const float* c1b = (const float*)d_in[19];
    const float* cg  = (const float*)d_in[20];
    const float* cb  = (const float*)d_in[21];
    const float* c2W = (const float*)d_in[22];
    const float* c2b = (const float*)d_in[23];
    float* out = (float*)d_out;

    float *p_h1, *p_h2, *p_s1, *p_s2;
    __half* p_m;
    cudaGetSymbolAddress((void**)&p_h1, g_h1);
    cudaGetSymbolAddress((void**)&p_h2, g_h2);
    cudaGetSymbolAddress((void**)&p_s1, g_stats1);
    cudaGetSymbolAddress((void**)&p_s2, g_stats2);
    cudaGetSymbolAddress((void**)&p_m, g_mh);

    cudaFuncSetAttribute(k_gemm, cudaFuncAttributeMaxDynamicSharedMemorySize, DYN_BYTES);
    cudaFuncSetAttribute(k_post, cudaFuncAttributeMaxDynamicSharedMemorySize, DYN_BYTES);

    const int GEMM_BLKS = (NN + 63) / 64;
    const int E4_BLKS   = (EE / 4 + 255) / 256;
    const int WTS_BLKS  = (NN * 32 + 255) / 256;

    // CSR build with layer-1 GEMM interleaved
    k_zero<<<(NN + 256) / 256, 256>>>();
    k_deg<<<E4_BLKS, 256>>>(dst);
    k_scan1<<<NB1, 1024>>>();
    k_gemm<<<GEMM_BLKS, 256, DYN_BYTES>>>(feats, nullptr, nullptr, nullptr, W0, p_m);
    k_scan2<<<1, 128>>>();
    k_scatter<<<E4_BLKS, 256>>>(src, dst);

    // layer 1 (rest)
    k_post<<<GEMM_BLKS, 256, DYN_BYTES>>>(feats, nullptr, nullptr, nullptr, rW0, rb0, b0, p_h1, p_s1);

    // layer 2
    k_gemm<<<GEMM_BLKS, 256, DYN_BYTES>>>(p_h1, p_s1, g0, be0, W1, p_m);
    k_post<<<GEMM_BLKS, 256, DYN_BYTES>>>(p_h1, p_s1, g0, be0, rW1, rb1, b1, p_h2, p_s2);

    // pooling
    k_wts<<<WTS_BLKS, 256>>>(g1, be1, awW, awb);
    k_pool<<<NG, 64>>>(ngr, g1, be1);

    // classifier head
    k_cls1<<<NG / 8, 128>>>(c1W, c1b);
    k_cls2<<<(NG * NT + 255) / 256, 256>>>(cg, cb, c2W, c2b, out);
}

// round 12
// speedup vs baseline: 1.2593x; 1.2593x over previous
// R12: R10 base + tensor-core k_gemm (mma.sync m16n8k16, fp16 in / fp32 accum).
#include <cuda_runtime.h>
#include <cuda_fp16.h>
#include <math.h>
#include <float.h>

#define NN 100000
#define EE 1200000
#define FD 64
#define NG 1024
#define NT 12
#define CHID 128
#define EPS 1e-5f
#define NB1 98   // (NN+1023)/1024

// ---------------- scratch ----------------
__device__ __half g_mh[(size_t)NN * FD];  // projected messages (fp16)
__device__ float g_h1[(size_t)NN * FD];
__device__ float g_h2[(size_t)NN * FD];
__device__ float g_w[NN];
__device__ int   g_deg[NN + 1];
__device__ int   g_off[NN + 1];
__device__ int   g_cur[NN];
__device__ int   g_esrc[EE];
__device__ int   g_bsum[128];
__device__ int   g_bpre[128];
__device__ float g_stats1[2 * FD];
__device__ float g_stats2[2 * FD];
__device__ float g_statsC[2 * CHID];
__device__ float g_hg[(size_t)NG * 2 * FD];
__device__ float g_z[(size_t)NG * CHID];

// ---------------- zero ----------------
__global__ void k_zero() {
    int i = blockIdx.x * blockDim.x + threadIdx.x;
    if (i < NN + 1) g_deg[i] = 0;
    if (i < NN) g_cur[i] = 0;
    if (i < 2 * FD) { g_stats1[i] = 0.f; g_stats2[i] = 0.f; }
    if (i < 2 * CHID) g_statsC[i] = 0.f;
}

// ---------------- CSR build ----------------
__global__ void k_deg(const int* __restrict__ dst) {
    int i = blockIdx.x * blockDim.x + threadIdx.x;
    if (i < EE / 4) {
        int4 d = ((const int4*)dst)[i];
        atomicAdd(&g_deg[d.x], 1);
        atomicAdd(&g_deg[d.y], 1);
        atomicAdd(&g_deg[d.z], 1);
        atomicAdd(&g_deg[d.w], 1);
    }
}

__global__ __launch_bounds__(1024) void k_scan1() {
    int tid = threadIdx.x;
    int i = blockIdx.x * 1024 + tid;
    int d = (i < NN) ? g_deg[i] : 0;
    int lane = tid & 31, wid = tid >> 5;
    int v = d;
    #pragma unroll
    for (int o = 1; o < 32; o <<= 1) {
        int t = __shfl_up_sync(0xffffffffu, v, o);
        if (lane >= o) v += t;
    }
    __shared__ int ws[32];
    if (lane == 31) ws[wid] = v;
    __syncthreads();
    if (wid == 0) {
        int u = ws[lane];
        #pragma unroll
        for (int o = 1; o < 32; o <<= 1) {
            int t = __shfl_up_sync(0xffffffffu, u, o);
            if (lane >= o) u += t;
        }
        ws[lane] = u;
    }
    __syncthreads();
    int base = wid ? ws[wid - 1] : 0;
    if (i < NN) g_off[i] = base + v - d;
    if (tid == 0) g_bsum[blockIdx.x] = ws[31];
}

__global__ void k_scan2() {
    __shared__ int sh[128];
    int tid = threadIdx.x;
    int v = (tid < NB1) ? g_bsum[tid] : 0;
    sh[tid] = v;
    __syncthreads();
    for (int o = 1; o < 128; o <<= 1) {
        int t = (tid >= o) ? sh[tid - o] : 0;
        __syncthreads();
        sh[tid] += t;
        __syncthreads();
    }
    if (tid < NB1) g_bpre[tid] = sh[tid] - v;
}

__global__ void k_scatter(const int* __restrict__ src, const int* __restrict__ dst) {
    int i = blockIdx.x * blockDim.x + threadIdx.x;
    if (i < EE / 4) {
        int4 s = ((const int4*)src)[i];
        int4 d = ((const int4*)dst)[i];
        int o0 = __ldg(&g_off[d.x]) + __ldg(&g_bpre[d.x >> 10]);
        int o1 = __ldg(&g_off[d.y]) + __ldg(&g_bpre[d.y >> 10]);
        int o2 = __ldg(&g_off[d.z]) + __ldg(&g_bpre[d.z >> 10]);
        int o3 = __ldg(&g_off[d.w]) + __ldg(&g_bpre[d.w >> 10]);
        g_esrc[o0 + atomicAdd(&g_cur[d.x], 1)] = s.x;
        g_esrc[o1 + atomicAdd(&g_cur[d.y], 1)] = s.y;
        g_esrc[o2 + atomicAdd(&g_cur[d.z], 1)] = s.z;
        g_esrc[o3 + atomicAdd(&g_cur[d.w], 1)] = s.w;
    }
}

__device__ __forceinline__ int node_off(int v) {
    return g_off[v] + g_bpre[v >> 10];
}

// ---------------- tensor-core GEMM: m = BN(x) @ W -> fp16 ----------------
__device__ __forceinline__ void mma16816(float c[4],
    unsigned a0, unsigned a1, unsigned a2, unsigned a3,
    unsigned b0, unsigned b1)
{
    asm volatile(
        "mma.sync.aligned.m16n8k16.row.col.f32.f16.f16.f32 "
        "{%0,%1,%2,%3}, {%4,%5,%6,%7}, {%8,%9}, {%0,%1,%2,%3};"
        : "+f"(c[0]), "+f"(c[1]), "+f"(c[2]), "+f"(c[3])
        : "r"(a0), "r"(a1), "r"(a2), "r"(a3), "r"(b0), "r"(b1));
}

__global__ __launch_bounds__(256) void k_gemm(
    const float* __restrict__ x,
    const float* __restrict__ stats, const float* __restrict__ gamma, const float* __restrict__ beta,
    const float* __restrict__ W, __half* __restrict__ out)
{
    __shared__ __half xh[64][72];
    __shared__ __half Wh[64][72];
    __shared__ float scb[64], shb[64];
    int tid = threadIdx.x;

    if (tid < 64) {
        float sc = 1.f, sh = 0.f;
        if (stats) {
            float mu  = stats[tid] * (1.f / NN);
            float var = stats[64 + tid] * (1.f / NN) - mu * mu;
            float rs  = rsqrtf(var + EPS);
            sc = gamma[tid] * rs;
            sh = beta[tid] - mu * sc;
        }
        scb[tid] = sc; shb[tid] = sh;
    }
    // W [k][n] fp32 -> Wh fp16
    #pragma unroll
    for (int q = 0; q < 16; q++) {
        int lin = tid + q * 256;
        Wh[lin >> 6][lin & 63] = __float2half(W[lin]);
    }
    __syncthreads();

    int row0 = blockIdx.x * 64;
    #pragma unroll
    for (int q = 0; q < 4; q++) {
        int lin = tid + q * 256;
        int r = lin >> 4;
        int c4 = (lin & 15) * 4;
        float4 v = make_float4(0.f, 0.f, 0.f, 0.f);
        if (row0 + r < NN) v = *(const float4*)(x + (size_t)(row0 + r) * 64 + c4);
        __half2 p0 = __floats2half2_rn(v.x * scb[c4 + 0] + shb[c4 + 0],
                                       v.y * scb[c4 + 1] + shb[c4 + 1]);
        __half2 p1 = __floats2half2_rn(v.z * scb[c4 + 2] + shb[c4 + 2],
                                       v.w * scb[c4 + 3] + shb[c4 + 3]);
        *(unsigned*)&xh[r][c4 + 0] = *(unsigned*)&p0;
        *(unsigned*)&xh[r][c4 + 2] = *(unsigned*)&p1;
    }
    __syncthreads();

    int w = tid >> 5, lane = tid & 31;
    int g = lane >> 2, tig = lane & 3;
    int rg = w & 3, cg = w >> 2;            // 4 row-groups x 2 col-groups
    int rowA = rg * 16;
    float c[4][4] = {};                      // [n-tile][c0..c3]

    #pragma unroll
    for (int k0 = 0; k0 < 64; k0 += 16) {
        unsigned a0 = *(unsigned*)&xh[rowA + g][k0 + tig * 2];
        unsigned a1 = *(unsigned*)&xh[rowA + g + 8][k0 + tig * 2];
        unsigned a2 = *(unsigned*)&xh[rowA + g][k0 + tig * 2 + 8];
        unsigned a3 = *(unsigned*)&xh[rowA + g + 8][k0 + tig * 2 + 8];
        #pragma unroll
        for (int nt = 0; nt < 4; nt++) {
            int n = cg * 32 + nt * 8 + g;
            __half2 b0 = __halves2half2(Wh[k0 + tig * 2][n],     Wh[k0 + tig * 2 + 1][n]);
            __half2 b1 = __halves2half2(Wh[k0 + tig * 2 + 8][n], Wh[k0 + tig * 2 + 9][n]);
            mma16816(c[nt], a0, a1, a2, a3, *(unsigned*)&b0, *(unsigned*)&b1);
        }
    }

    #pragma unroll
    for (int nt = 0; nt < 4; nt++) {
        int n = cg * 32 + nt * 8 + tig * 2;
        int r0g = row0 + rowA + g;
        if (r0g < NN) {
            __half2 h = __floats2half2_rn(c[nt][0], c[nt][1]);
            *(unsigned*)&out[(size_t)r0g * 64 + n] = *(unsigned*)&h;
        }
        int r1g = r0g + 8;
        if (r1g < NN) {
            __half2 h = __floats2half2_rn(c[nt][2], c[nt][3]);
            *(unsigned*)&out[(size_t)r1g * 64 + n] = *(unsigned*)&h;
        }
    }
}

// ---- post (fused): residual fp32 GEMM + quarter-warp fp16 gather + bias/relu + BN stats ----
__global__ __launch_bounds__(256) void k_post(
    const float* __restrict__ x,
    const float* __restrict__ stats, const float* __restrict__ gamma, const float* __restrict__ beta,
    const float* __restrict__ rW, const float* __restrict__ rb, const float* __restrict__ bias,
    float* __restrict__ outh, float* __restrict__ stats_out)
{
    __shared__ float xs[64][68];
    __shared__ float Ws[64][64];           // rW during k-loop, then agg tile
    __shared__ float scb[64], shb[64];
    __shared__ float s_sum[64], s_sq[64];
    int tid = threadIdx.x;
    int lane = tid & 31, wi = tid >> 5;

    if (tid < 64) {
        float sc = 1.f, sh = 0.f;
        if (stats) {
            float mu  = stats[tid] * (1.f / NN);
            float var = stats[64 + tid] * (1.f / NN) - mu * mu;
            float rs  = rsqrtf(var + EPS);
            sc = gamma[tid] * rs;
            sh = beta[tid] - mu * sc;
        }
        scb[tid] = sc; shb[tid] = sh;
        s_sum[tid] = 0.f; s_sq[tid] = 0.f;
    }
    #pragma unroll
    for (int q = 0; q < 16; q++) {
        int lin = tid + q * 256;
        ((float*)Ws)[lin] = rW[lin];
    }
    __syncthreads();

    int row0 = blockIdx.x * 64;
    #pragma unroll
    for (int q = 0; q < 4; q++) {
        int lin = tid + q * 256;
        int r = lin >> 4;
        int c4 = (lin & 15) * 4;
        float4 v = make_float4(0.f, 0.f, 0.f, 0.f);
        if (row0 + r < NN) v = *(const float4*)(x + (size_t)(row0 + r) * 64 + c4);
        float4 o;
        o.x = v.x * scb[c4 + 0] + shb[c4 + 0];
        o.y = v.y * scb[c4 + 1] + shb[c4 + 1];
        o.z = v.z * scb[c4 + 2] + shb[c4 + 2];
        o.w = v.w * scb[c4 + 3] + shb[c4 + 3];
        *(float4*)&xs[r][c4] = o;
    }
    __syncthreads();

    int tx = tid & 15, ty = tid >> 4;
    int r0 = ty * 4, c0 = tx * 4;
    float acc[4][4] = {};
    #pragma unroll 4
    for (int k4 = 0; k4 < 64; k4 += 4) {
        float4 av[4];
        av[0] = *(const float4*)&xs[r0 + 0][k4];
        av[1] = *(const float4*)&xs[r0 + 1][k4];
        av[2] = *(const float4*)&xs[r0 + 2][k4];
        av[3] = *(const float4*)&xs[r0 + 3][k4];
        #pragma unroll
        for (int kk = 0; kk < 4; kk++) {
            float4 b = *(const float4*)&Ws[k4 + kk][c0];
            #pragma unroll
            for (int i = 0; i < 4; i++) {
                float a = (&av[i].x)[kk];
                acc[i][0] += a * b.x; acc[i][1] += a * b.y;
                acc[i][2] += a * b.z; acc[i][3] += a * b.w;
            }
        }
    }
    __syncthreads();   // done with rW in Ws

    // ---- gather: warp split into four 8-lane quarters, one node each; uint4/lane = full row ----
    float* aggs = &Ws[0][0];
    const uint4* m8 = (const uint4*)g_mh;           // 8 uint4 per node row (128 B)
    int lane8 = lane & 7;
    int qb    = lane & 24;                           // quarter base lane: 0,8,16,24
    for (int t = 0; t < 2; t++) {
        int r = wi * 8 + t * 4 + (qb >> 3);
        int v = row0 + r;
        float a0 = 0.f, a1 = 0.f, a2 = 0.f, a3 = 0.f;
        float a4 = 0.f, a5 = 0.f, a6 = 0.f, a7 = 0.f;
        int s = 0, cnt = 0;
        if (v < NN) {
            s = node_off(v);
            int e = (v + 1 < NN) ? node_off(v + 1) : EE;
            cnt = e - s;
        }
        int m = max(cnt, __shfl_xor_sync(0xffffffffu, cnt, 8));
        int iters = max(m, __shfl_xor_sync(0xffffffffu, m, 16));
        for (int base = 0; base < iters; base += 8) {
            int my = base + lane8;
            int idx = (my < cnt) ? __ldg(&g_esrc[s + my]) : -1;
            #pragma unroll
            for (int g = 0; g < 8; g += 4) {
                int s0 = __shfl_sync(0xffffffffu, idx, qb + g + 0);
                int s1 = __shfl_sync(0xffffffffu, idx, qb + g + 1);
                int s2 = __shfl_sync(0xffffffffu, idx, qb + g + 2);
                int s3 = __shfl_sync(0xffffffffu, idx, qb + g + 3);
                uint4 z = make_uint4(0u, 0u, 0u, 0u);
                uint4 q0 = (s0 >= 0) ? __ldg(&m8[(size_t)s0 * 8 + lane8]) : z;
                uint4 q1 = (s1 >= 0) ? __ldg(&m8[(size_t)s1 * 8 + lane8]) : z;
                uint4 q2 = (s2 >= 0) ? __ldg(&m8[(size_t)s2 * 8 + lane8]) : z;
                uint4 q3 = (s3 >= 0) ? __ldg(&m8[(size_t)s3 * 8 + lane8]) : z;
                float2 f0, f1, f2, f3;
                f0 = __half22float2(*(__half2*)&q0.x); f1 = __half22float2(*(__half2*)&q1.x);
                f2 = __half22float2(*(__half2*)&q2.x); f3 = __half22float2(*(__half2*)&q3.x);
                a0 += (f0.x + f1.x) + (f2.x + f3.x);
                a1 += (f0.y + f1.y) + (f2.y + f3.y);
                f0 = __half22float2(*(__half2*)&q0.y); f1 = __half22float2(*(__half2*)&q1.y);
                f2 = __half22float2(*(__half2*)&q2.y); f3 = __half22float2(*(__half2*)&q3.y);
                a2 += (f0.x + f1.x) + (f2.x + f3.x);
                a3 += (f0.y + f1.y) + (f2.y + f3.y);
                f0 = __half22float2(*(__half2*)&q0.z); f1 = __half22float2(*(__half2*)&q1.z);
                f2 = __half22float2(*(__half2*)&q2.z); f3 = __half22float2(*(__half2*)&q3.z);
                a4 += (f0.x + f1.x) + (f2.x + f3.x);
                a5 += (f0.y + f1.y) + (f2.y + f3.y);
                f0 = __half22float2(*(__half2*)&q0.w); f1 = __half22float2(*(__half2*)&q1.w);
                f2 = __half22float2(*(__half2*)&q2.w); f3 = __half22float2(*(__half2*)&q3.w);
                a6 += (f0.x + f1.x) + (f2.x + f3.x);
                a7 += (f0.y + f1.y) + (f2.y + f3.y);
            }
        }
        if (v < NN) {
            float* dst = aggs + r * 64 + lane8 * 8;
            *(float4*)(dst + 0) = make_float4(a0, a1, a2, a3);
            *(float4*)(dst + 4) = make_float4(a4, a5, a6, a7);
        }
    }
    __syncthreads();

    // ---- epilogue ----
    float4 b4  = *(const float4*)(bias + c0);
    float4 rb4 = *(const float4*)(rb + c0);
    float lsum[4] = {0.f, 0.f, 0.f, 0.f};
    float lsq[4]  = {0.f, 0.f, 0.f, 0.f};
    #pragma unroll
    for (int i = 0; i < 4; i++) {
        int r = row0 + r0 + i;
        if (r < NN) {
            float4 av = *(const float4*)(aggs + (r0 + i) * 64 + c0);
            float h0 = fmaxf(av.x + b4.x, 0.f) + fmaxf(acc[i][0] + rb4.x, 0.f);
            float h1 = fmaxf(av.y + b4.y, 0.f) + fmaxf(acc[i][1] + rb4.y, 0.f);
            float h2 = fmaxf(av.z + b4.z, 0.f) + fmaxf(acc[i][2] + rb4.z, 0.f);
            float h3 = fmaxf(av.w + b4.w, 0.f) + fmaxf(acc[i][3] + rb4.w, 0.f);
            *(float4*)(outh + (size_t)r * 64 + c0) = make_float4(h0, h1, h2, h3);
            lsum[0] += h0; lsq[0] += h0 * h0;
            lsum[1] += h1; lsq[1] += h1 * h1;
            lsum[2] += h2; lsq[2] += h2 * h2;
            lsum[3] += h3; lsq[3] += h3 * h3;
        }
    }
    #pragma unroll
    for (int j = 0; j < 4; j++) {
        atomicAdd(&s_sum[c0 + j], lsum[j]);
        atomicAdd(&s_sq[c0 + j], lsq[j]);
    }
    __syncthreads();
    if (tid < 64) {
        atomicAdd(&stats_out[tid], s_sum[tid]);
        atomicAdd(&stats_out[64 + tid], s_sq[tid]);
    }
}

// ---------------- atom weights ----------------
__global__ __launch_bounds__(256) void k_wts(
    const float* __restrict__ gamma, const float* __restrict__ beta,
    const float* __restrict__ awW, const float* __restrict__ awb)
{
    int gt = blockIdx.x * blockDim.x + threadIdx.x;
    int v = gt >> 5;
    int lane = gt & 31;
    if (v >= NN) return;
    int f0 = 2 * lane, f1 = f0 + 1;
    float mu0  = g_stats2[f0] * (1.f / NN);
    float var0 = g_stats2[64 + f0] * (1.f / NN) - mu0 * mu0;
    float sc0  = gamma[f0] * rsqrtf(var0 + EPS);
    float sh0  = beta[f0] - mu0 * sc0;
    float mu1  = g_stats2[f1] * (1.f / NN);
    float var1 = g_stats2[64 + f1] * (1.f / NN) - mu1 * mu1;
    float sc1  = gamma[f1] * rsqrtf(var1 + EPS);
    float sh1  = beta[f1] - mu1 * sc1;
    float2 h = ((const float2*)g_h2)[(size_t)v * 32 + lane];
    float p = (h.x * sc0 + sh0) * awW[f0] + (h.y * sc1 + sh1) * awW[f1];
    #pragma unroll
    for (int o = 16; o; o >>= 1) p += __shfl_down_sync(0xffffffffu, p, o);
    if (lane == 0) g_w[v] = 1.f / (1.f + __expf(-(p + awb[0])));
}

// ---------------- pooling ----------------
__global__ __launch_bounds__(64) void k_pool(
    const int* __restrict__ ngr,
    const float* __restrict__ gamma, const float* __restrict__ beta)
{
    int g = blockIdx.x;
    int j = threadIdx.x;
    __shared__ int bnd[2];
    if (j < 2) {
        int key = g + j;
        int lo = 0, hi = NN;
        while (lo < hi) {
            int mid = (lo + hi) >> 1;
            if (ngr[mid] < key) lo = mid + 1; else hi = mid;
        }
        bnd[j] = lo;
    }
    float mu  = g_stats2[j] * (1.f / NN);
    float var = g_stats2[64 + j] * (1.f / NN) - mu * mu;
    float rs  = rsqrtf(var + EPS);
    float sc  = gamma[j] * rs;
    float sh  = beta[j] - mu * sc;
    __syncthreads();

    int s = bnd[0], e = bnd[1];
    float sum = 0.f, mx = -FLT_MAX;
    int n = s;
    for (; n + 4 <= e; n += 4) {
        float h0 = g_h2[(size_t)(n + 0) * 64 + j];
        float h1 = g_h2[(size_t)(n + 1) * 64 + j];
        float h2 = g_h2[(size_t)(n + 2) * 64 + j];
        float h3 = g_h2[(size_t)(n + 3) * 64 + j];
        float w0 = __ldg(&g_w[n + 0]);
        float w1 = __ldg(&g_w[n + 1]);
        float w2 = __ldg(&g_w[n + 2]);
        float w3 = __ldg(&g_w[n + 3]);
        h0 = h0 * sc + sh; h1 = h1 * sc + sh; h2 = h2 * sc + sh; h3 = h3 * sc + sh;
        sum += h0 * w0 + h1 * w1 + h2 * w2 + h3 * w3;
        mx = fmaxf(fmaxf(fmaxf(mx, h0), fmaxf(h1, h2)), h3);
    }
    for (; n < e; n++) {
        float h = g_h2[(size_t)n * 64 + j] * sc + sh;
        sum += h * __ldg(&g_w[n]);
        mx = fmaxf(mx, h);
    }
    g_hg[(size_t)g * 128 + j]      = sum;
    g_hg[(size_t)g * 128 + 64 + j] = mx;
}

// ---------------- classifier layer 1 ----------------
__global__ __launch_bounds__(128) void k_cls1(const float* __restrict__ W, const float* __restrict__ b) {
    __shared__ float xs[8][128];
    int tid = threadIdx.x;
    int row0 = blockIdx.x * 8;
    #pragma unroll
    for (int q = 0; q < 8; q++) {
        int lin = tid + q * 128;
        xs[lin >> 7][lin & 127] = g_hg[(size_t)row0 * 128 + lin];
    }
    __syncthreads();
    int j = tid;
    float acc[8] = {};
    for (int k = 0; k < 128; k++) {
        float w = __ldg(&W[k * 128 + j]);
        #pragma unroll
        for (int r = 0; r < 8; r++) acc[r] += xs[r][k] * w;
    }
    float bj = b[j];
    float lsum = 0.f, lsq = 0.f;
    #pragma unroll
    for (int r = 0; r < 8; r++) {
        float z = fmaxf(acc[r] + bj, 0.f);
        g_z[(size_t)(row0 + r) * 128 + j] = z;
        lsum += z; lsq += z * z;
    }
    atomicAdd(&g_statsC[j], lsum);
    atomicAdd(&g_statsC[128 + j], lsq);
}

// ---------------- classifier layer 2 ----------------
__global__ __launch_bounds__(256) void k_cls2(
    const float* __restrict__ cg, const float* __restrict__ cb,
    const float* __restrict__ W2, const float* __restrict__ b2, float* __restrict__ out)
{
    __shared__ float sc[128], sh[128];
    int tid = threadIdx.x;
    if (tid < 128) {
        float mu  = g_statsC[tid] * (1.f / NG);
        float var = g_statsC[128 + tid] * (1.f / NG) - mu * mu;
        float rs  = rsqrtf(var + EPS);
        float s = cg[tid] * rs;
        sc[tid] = s;
        sh[tid] = cb[tid] - mu * s;
    }
    __syncthreads();
    int idx = blockIdx.x * 256 + tid;
    if (idx >= NG * NT) return;
    int r = idx / NT, t = idx - r * NT;
    float acc = b2[t];
    for (int k = 0; k < 128; k++)
        acc += (g_z[(size_t)r * 128 + k] * sc[k] + sh[k]) * __ldg(&W2[k * NT + t]);
    out[idx] = acc;
}

// ---------------- launch (single stream, graph-capture safe) ----------------
extern "C" void kernel_launch(void* const* d_in, const int* in_sizes, int n_in,
                              void* d_out, int out_size) {
    const float* feats = (const float*)d_in[0];
    const int*   src   = (const int*)d_in[1];
    const int*   dst   = (const int*)d_in[2];
    const int*   ngr   = (const int*)d_in[3];
    const float* W0  = (const float*)d_in[4];
    const float* b0  = (const float*)d_in[5];
    const float* rW0 = (const float*)d_in[6];
    const float* rb0 = (const float*)d_in[7];
    const float* g0  = (const float*)d_in[8];
    const float* be0 = (const float*)d_in[9];
    const float* W1  = (const float*)d_in[10];
    const float* b1  = (const float*)d_in[11];
    const float* rW1 = (const float*)d_in[12];
    const float* rb1 = (const float*)d_in[13];
    const float* g1  = (const float*)d_in[14];
    const float* be1 = (const float*)d_in[15];
    const float* awW = (const float*)d_in[16];
    const float* awb = (const float*)d_in[17];
    const float* c1W = (const float*)d_in[18];
    const float* c1b = (const float*)d_in[19];
    const float* cg  = (const float*)d_in[20];
    const float* cb  = (const float*)d_in[21];
    const float* c2W = (const float*)d_in[22];
    const float* c2b = (const float*)d_in[23];
    float* out = (float*)d_out;

    float *p_h1, *p_h2, *p_s1, *p_s2;
    __half* p_m;
    cudaGetSymbolAddress((void**)&p_h1, g_h1);
    cudaGetSymbolAddress((void**)&p_h2, g_h2);
    cudaGetSymbolAddress((void**)&p_s1, g_stats1);
    cudaGetSymbolAddress((void**)&p_s2, g_stats2);
    cudaGetSymbolAddress((void**)&p_m, g_mh);

    const int GEMM_BLKS = (NN + 63) / 64;
    const int E4_BLKS   = (EE / 4 + 255) / 256;
    const int WTS_BLKS  = (NN * 32 + 255) / 256;

    // CSR build with layer-1 GEMM interleaved
    k_zero<<<(NN + 256) / 256, 256>>>();
    k_deg<<<E4_BLKS, 256>>>(dst);
    k_scan1<<<NB1, 1024>>>();
    k_gemm<<<GEMM_BLKS, 256>>>(feats, nullptr, nullptr, nullptr, W0, p_m);
    k_scan2<<<1, 128>>>();
    k_scatter<<<E4_BLKS, 256>>>(src, dst);

    // layer 1 (rest)
    k_post<<<GEMM_BLKS, 256>>>(feats, nullptr, nullptr, nullptr, rW0, rb0, b0, p_h1, p_s1);

    // layer 2
    k_gemm<<<GEMM_BLKS, 256>>>(p_h1, p_s1, g0, be0, W1, p_m);
    k_post<<<GEMM_BLKS, 256>>>(p_h1, p_s1, g0, be0, rW1, rb1, b1, p_h2, p_s2);

    // pooling
    k_wts<<<WTS_BLKS, 256>>>(g1, be1, awW, awb);
    k_pool<<<NG, 64>>>(ngr, g1, be1);

    // classifier head
    k_cls1<<<NG / 8, 128>>>(c1W, c1b);
    k_cls2<<<(NG * NT + 255) / 256, 256>>>(cg, cb, c2W, c2b, out);
}